// round 15
// baseline (speedup 1.0000x reference)
#include <cuda_runtime.h>

#define NB 16
#define NC 64
#define HW 65536
#define NBINS 256
#define NA   128            // stage A blocks: 2 per plane
#define NCOS 256            // BC blocks that do cos (64 px x 4 quarters)
#define NBC  320            // all BC blocks do mul; stride 320*256 = 5*16384
#define NBLK (NA + NBC)     // 448

// ---- scratch (no allocations allowed) ----
__device__ float         d_part[NB * NC * 2];   // per-(plane,half) partial sums
__device__ unsigned int  d_hist[NB * NBINS];
__device__ float         d_scale[NB * NBINS];
__device__ unsigned char d_q[NB * HW];
__device__ unsigned int  d_cA[NB];              // A arrivals   (==NA: sums ready)
__device__ unsigned int  d_cH[NB];              // cos arrivals (==NCOS+1: LUT ready)
__device__ unsigned int  d_cM[NB];              // mul arrivals (==NBC: batch written)

__global__ void k_init() {
    d_hist[blockIdx.x * NBINS + threadIdx.x] = 0u;
    if (threadIdx.x == 0) {
        d_cA[blockIdx.x] = 0u; d_cH[blockIdx.x] = 0u; d_cM[blockIdx.x] = 0u;
    }
}

__device__ __forceinline__ void spin_ge(const unsigned int* p, unsigned int v) {
    const volatile unsigned int* vp = (const volatile unsigned int*)p;
    while (*vp < v) { }
}

// mul one batch: pure stream, per-thread scale hoisted (p4 loop-invariant)
__device__ __forceinline__ void do_mul(const float* __restrict__ F,
                                       float* __restrict__ out,
                                       int b, int idx0, int p4) {
    uchar4 qv = *(const uchar4*)(d_q + ((size_t)b << 16) + ((size_t)p4 << 2));
    const float* sc = d_scale + b * NBINS;               // 1 KB, L2-hot
    const float sx = __ldg(sc + qv.x), sy = __ldg(sc + qv.y);
    const float sz = __ldg(sc + qv.z), sw = __ldg(sc + qv.w);
    const float4* Fb = (const float4*)F + ((size_t)b << 20);
    float4*       Ob = (float4*)out + ((size_t)b << 20);
    #pragma unroll 4
    for (int idx = idx0; idx < (1 << 20); idx += NBC * 256) {
        float4 v = __ldcs(Fb + idx);                     // last use: evict-first
        float4 o;
        o.x = v.x * sx; o.y = v.y * sy; o.z = v.z * sz; o.w = v.w * sw;
        __stcs(Ob + idx, o);                             // streaming store
    }
}

// ============================================================
// A: mean partials, 2 slots ahead.  BC: cos+hist(b) then mul(b-1).
// Steady state: every gate's producer finished a slot earlier -> no waits.
// ============================================================
__global__ void __launch_bounds__(256, 4) k_pipe(const float* __restrict__ F,
                                                 float* __restrict__ out) {
    const int tid = threadIdx.x;
    const int bid = blockIdx.x;

    __shared__ float        sPart[8 * 256];
    __shared__ float        sA[NBINS];
    __shared__ unsigned int sU[NBINS];
    __shared__ int          sLast;

    if (bid < NA) {
        // ================= Stage A: plane-mean partials ==================
        const int c = bid >> 1, half = bid & 1;
        for (int b = 0; b < NB; ++b) {
            if (b >= 3) {                    // <=3 live slabs (48 MB) in L2
                if (tid == 0) spin_ge(&d_cM[b - 3], NBC);
                __syncthreads();
            }
            const float4* base = (const float4*)F +
                ((size_t)(b * NC + c) << 14) + ((size_t)half << 13);
            float s = 0.f;
            #pragma unroll 8
            for (int j = 0; j < 32; ++j) {   // 8192 float4 / 256 thr
                float4 v = __ldcg(base + j * 256 + tid);   // fill L2, skip L1
                s += (v.x + v.y) + (v.z + v.w);
            }
            sPart[tid] = s;
            __syncthreads();
            for (int o = 128; o > 0; o >>= 1) {
                if (tid < o) sPart[tid] += sPart[tid + o];
                __syncthreads();
            }
            if (tid == 0) {
                d_part[(b * NC + c) * 2 + half] = sPart[0];
                __threadfence();
                atomicAdd(&d_cA[b], 1u);
            }
            __syncthreads();
        }
    } else {
        // ================= Stage BC ==================
        const int sub  = bid - NA;                   // 0..319
        const int idx0 = (sub << 8) + tid;           // mul: < 81920
        const int mp4  = idx0 & 16383;               // invariant pixel for mul
        int prevb = -1;

        for (int b = 0; b < NB; ++b) {
            if (sub < NCOS) {
                // ---- cos + quantize + hist (64 px, 4 channel-quarters) ----
                if (tid == 0) spin_ge(&d_cA[b], NA);
                __syncthreads();
                __threadfence();

                if (tid < NC)
                    sA[tid] = (d_part[(b * NC + tid) * 2] +
                               d_part[(b * NC + tid) * 2 + 1]) * (1.0f / HW);
                sU[tid] = 0u;
                __syncthreads();
                sPart[tid] = (tid < NC) ? sA[tid] * sA[tid] : 0.f;
                __syncthreads();
                for (int o = 128; o > 0; o >>= 1) {
                    if (tid < o) sPart[tid] += sPart[tid + o];
                    __syncthreads();
                }
                const float inv = 1.0f / fmaxf(sqrtf(sPart[0]), 1e-12f);
                __syncthreads();
                if (tid < NC) sA[tid] *= inv;
                __syncthreads();

                const int p4 = (sub << 6) + (tid & 63);
                const int c0 = (tid >> 6) << 4;      // quarter: 16 channels
                const float4* fp = (const float4*)F + ((size_t)b << 20) + p4;
                float d0 = 0.f, d1 = 0.f, d2 = 0.f, d3 = 0.f;
                float s0 = 0.f, s1 = 0.f, s2 = 0.f, s3 = 0.f;
                #pragma unroll 8
                for (int i = 0; i < 16; ++i) {
                    float4 v = fp[(size_t)(c0 + i) << 14];
                    float ac = sA[c0 + i];
                    d0 += ac * v.x; d1 += ac * v.y; d2 += ac * v.z; d3 += ac * v.w;
                    s0 += v.x * v.x; s1 += v.y * v.y; s2 += v.z * v.z; s3 += v.w * v.w;
                }
                sPart[0 * 256 + tid] = d0; sPart[1 * 256 + tid] = d1;
                sPart[2 * 256 + tid] = d2; sPart[3 * 256 + tid] = d3;
                sPart[4 * 256 + tid] = s0; sPart[5 * 256 + tid] = s1;
                sPart[6 * 256 + tid] = s2; sPart[7 * 256 + tid] = s3;
                __syncthreads();

                if (tid < 64) {
                    float r[8];
                    #pragma unroll
                    for (int k = 0; k < 8; ++k)
                        r[k] = ((sPart[k * 256 + tid]       + sPart[k * 256 + tid + 64]) +
                                (sPart[k * 256 + tid + 128] + sPart[k * 256 + tid + 192]));
                    int q0 = ((int)((r[0] / fmaxf(sqrtf(r[4]), 1e-12f)) * 255.0f)) & 255;
                    int q1 = ((int)((r[1] / fmaxf(sqrtf(r[5]), 1e-12f)) * 255.0f)) & 255;
                    int q2 = ((int)((r[2] / fmaxf(sqrtf(r[6]), 1e-12f)) * 255.0f)) & 255;
                    int q3 = ((int)((r[3] / fmaxf(sqrtf(r[7]), 1e-12f)) * 255.0f)) & 255;
                    atomicAdd(&sU[q0], 1u); atomicAdd(&sU[q1], 1u);
                    atomicAdd(&sU[q2], 1u); atomicAdd(&sU[q3], 1u);
                    const int myp4 = (sub << 6) + tid;
                    *(uchar4*)(d_q + ((size_t)b << 16) + ((size_t)myp4 << 2)) =
                        make_uchar4((unsigned char)q0, (unsigned char)q1,
                                    (unsigned char)q2, (unsigned char)q3);
                }
                __syncthreads();
                unsigned int cnt = sU[tid];
                if (cnt) atomicAdd(&d_hist[b * NBINS + tid], cnt);
                __syncthreads();

                if (tid == 0) {
                    __threadfence();
                    sLast = (atomicAdd(&d_cH[b], 1u) == NCOS - 1);
                }
                __syncthreads();

                if (sLast) {                 // last cos block: build LUT
                    __threadfence();
                    float h = (float)d_hist[b * NBINS + tid];
                    float* cdf = sPart;
                    float* tmp = sPart + 256;
                    cdf[tid] = h;
                    __syncthreads();
                    for (int o = 1; o < NBINS; o <<= 1) {
                        float v = cdf[tid];
                        float add = (tid >= o) ? cdf[tid - o] : 0.f;
                        __syncthreads();
                        cdf[tid] = v + add;
                        __syncthreads();
                    }
                    tmp[tid] = (h > 0.f) ? cdf[tid] : (float)(HW + 1);
                    __syncthreads();
                    for (int o = 128; o > 0; o >>= 1) {
                        if (tid < o) tmp[tid] = fminf(tmp[tid], tmp[tid + o]);
                        __syncthreads();
                    }
                    float cmin  = tmp[0];
                    float denom = fmaxf((float)HW - cmin, 1.0f);
                    float lut   = rintf((cdf[tid] - cmin) * (255.0f / denom));
                    lut = fminf(fmaxf(lut, 0.0f), 255.0f);
                    d_scale[b * NBINS + tid] = lut * (1.0f / 255.0f);
                    __syncthreads();
                    if (tid == 0) {
                        __threadfence();
                        atomicAdd(&d_cH[b], 1u);     // -> NCOS+1 : LUT ready
                    }
                }
                __syncthreads();
            }

            // ---- mul(prevb): its LUT finished during the previous slot ----
            if (prevb >= 0) {
                if (tid == 0) spin_ge(&d_cH[prevb], NCOS + 1);
                __syncthreads();
                __threadfence();
                do_mul(F, out, prevb, idx0, mp4);
                __syncthreads();
                if (tid == 0) {
                    __threadfence();
                    atomicAdd(&d_cM[prevb], 1u);
                }
            }
            prevb = b;
        }

        // epilogue: mul for the last batch
        if (tid == 0) spin_ge(&d_cH[prevb], NCOS + 1);
        __syncthreads();
        __threadfence();
        do_mul(F, out, prevb, idx0, mp4);
    }
}

// ============================================================
extern "C" void kernel_launch(void* const* d_in, const int* in_sizes, int n_in,
                              void* d_out, int out_size) {
    const float* F = (const float*)d_in[0];
    float* out = (float*)d_out;
    (void)in_sizes; (void)n_in; (void)out_size;

    k_init<<<NB, NBINS>>>();
    k_pipe<<<NBLK, 256>>>(F, out);
}